// round 15
// baseline (speedup 1.0000x reference)
#include <cuda_runtime.h>
#include <cuda_bf16.h>
#include <cuda_fp16.h>
#include <math.h>

// Problem dims
#define BB 4
#define CC 16
#define FP 10
#define FA 30
#define SSEG 4
#define TT 2048
#define NBINS 18
#define KB17 17           // bins materialized per p (bin 17 derived)

#define NTH 512           // 16 warps
#define CK 128            // t per chunk
#define NCHUNK 16

// SMEM layout (bytes). A: 176 rows x 128 cols fp16, row stride 272 B. Two buffers.
// Rows: p*17+k (k<17) for p=0..9 -> 0..169; row 170 = all-ones totals row;
// rows 171..175 zero pad.
#define AST 272
#define MROWS 176
#define TOTROW 170
#define ABUF (MROWS*AST)          // 47872
#define B_OFF (2*ABUF)            // 95744; two B buffers: 32 x 272 fp16 each
#define BBUF 8704
#define BIN_OFF (B_OFF + 2*BBUF)  // 113152; 10*2048 bin bytes
#define ZERO_BYTES BIN_OFF
#define SMEM_BYTES (BIN_OFF + FP*TT)   // 133632
// Epilogue overlays A region (dead by then)
#define DRED_STRIDE (MROWS*33)    // floats
#define DFIN_OFF (3*MROWS*33*4)   // 69696 bytes

#define ONE_F16 0x3C00

__device__ float g_partial[BB*CC*FP*FA*SSEG];

__device__ __forceinline__ unsigned smem_u32(const void* p) {
    unsigned r;
    asm("{ .reg .u64 t; cvta.to.shared.u64 t, %1; cvt.u32.u64 %0, t; }"
        : "=r"(r) : "l"(p));
    return r;
}
__device__ __forceinline__ void ldsm_x4(unsigned addr, unsigned& r0, unsigned& r1,
                                        unsigned& r2, unsigned& r3) {
    asm volatile("ldmatrix.sync.aligned.m8n8.x4.shared.b16 {%0,%1,%2,%3}, [%4];"
                 : "=r"(r0), "=r"(r1), "=r"(r2), "=r"(r3) : "r"(addr));
}
__device__ __forceinline__ void mma16816(float* c, unsigned a0, unsigned a1,
                                         unsigned a2, unsigned a3,
                                         unsigned b0, unsigned b1) {
    asm volatile("mma.sync.aligned.m16n8k16.row.col.f32.f16.f16.f32 "
                 "{%0,%1,%2,%3}, {%4,%5,%6,%7}, {%8,%9}, {%0,%1,%2,%3};"
                 : "+f"(c[0]), "+f"(c[1]), "+f"(c[2]), "+f"(c[3])
                 : "r"(a0), "r"(a1), "r"(a2), "r"(a3), "r"(b0), "r"(b1));
}

// One chunk's MMA work for MT m-tiles (both k-halves of this warp's K slice).
template<int MT>
__device__ __forceinline__ void mma_steps(unsigned aAddrBase, unsigned bBase,
                                          int kg, unsigned nrow, unsigned kadd2,
                                          float acc[3][4][4]) {
    #pragma unroll
    for (int ks = 0; ks < 2; ++ks) {
        const int k0 = kg * 32 + ks * 16;
        unsigned a0[MT], a1[MT], a2[MT], a3[MT];
        #pragma unroll
        for (int mt = 0; mt < MT; ++mt)
            ldsm_x4(aAddrBase + mt * 16 * AST + k0 * 2, a0[mt], a1[mt], a2[mt], a3[mt]);
        unsigned bh[8];
        #pragma unroll
        for (int np = 0; np < 2; ++np) {
            const unsigned bOff = (unsigned)(np * 16 + nrow) * AST + k0 * 2 + kadd2;
            ldsm_x4(bBase + bOff, bh[np*4], bh[np*4+1], bh[np*4+2], bh[np*4+3]);
        }
        #pragma unroll
        for (int mt = 0; mt < MT; ++mt)
            #pragma unroll
            for (int nt = 0; nt < 4; ++nt) {
                const int bi = (nt >> 1) * 4 + (nt & 1) * 2;
                mma16816(acc[mt][nt], a0[mt], a1[mt], a2[mt], a3[mt], bh[bi], bh[bi+1]);
            }
    }
}

__device__ __forceinline__ void storeB_item(unsigned char* smem, float4 v, int item,
                                            int buf) {
    const int a = item >> 5, tq = item & 31;
    __half2 p01 = __floats2half2_rn(v.x, v.y);
    __half2 p23 = __floats2half2_rn(v.z, v.w);
    uint2 w = make_uint2(*(const unsigned*)&p01, *(const unsigned*)&p23);
    *(uint2*)(smem + B_OFF + buf * BBUF + a * AST + tq * 8) = w;
}

__global__ __launch_bounds__(NTH, 1)
void mi_mma_kernel(const float* __restrict__ pha, const float* __restrict__ amp)
{
    extern __shared__ __align__(16) unsigned char smem[];
    const unsigned sb = smem_u32(smem);
    const int tid = threadIdx.x, wid = tid >> 5, lane = tid & 31;
    const int bcs = blockIdx.x, s = bcs & 3, bc = bcs >> 2;
    const long phaBase = (long)bc * FP * (SSEG*TT) + (long)s * TT;
    const long ampBase = (long)bc * FA * (SSEG*TT) + (long)s * TT;
    unsigned char* binp = smem + BIN_OFF;

    // zero both A buffers + both B buffers
    for (int i = tid; i < ZERO_BYTES / 16; i += NTH)
        ((uint4*)smem)[i] = make_uint4(0, 0, 0, 0);

    // ---- phase 1: exact searchsorted bins -> binp[p*2048 + t] ----
    const float PI_F = 3.14159265358979323846f;
    const float step = __fdiv_rn(2.0f * PI_F, (float)NBINS);
    const float inv_step = 1.0f / step;
    #pragma unroll
    for (int p = 0; p < FP; ++p) {
        const float4 v4 = *(const float4*)(pha + phaBase + (long)p * (SSEG*TT) + (long)tid * 4);
        const float vv[4] = {v4.x, v4.y, v4.z, v4.w};
        uchar4 kb;
        unsigned char* kk = (unsigned char*)&kb;
        #pragma unroll
        for (int e = 0; e < 4; ++e) {
            const float v = vv[e];
            int k = (int)floorf((v + PI_F) * inv_step);
            k = min(max(k, 0), NBINS - 1);
            // guess is provably within +-1 bin: one exact fixup suffices
            {
                float ck  = __fadd_rn(-PI_F, __fmul_rn((float)k,       step));
                float ck1 = __fadd_rn(-PI_F, __fmul_rn((float)(k + 1), step));
                if (k > 0 && v <= ck)              k--;
                else if (k < NBINS - 1 && v > ck1) k++;
            }
            kk[e] = (unsigned char)k;
        }
        *(uchar4*)(binp + p * TT + tid * 4) = kb;
    }
    __syncthreads();

    // ones rows: B row 30 (counts channel) + A row 170 (totals row), both buffers
    if (tid < 256) {
        const int buf = tid >> 7, c = tid & 127;
        *(unsigned short*)(smem + B_OFF + buf * BBUF + 30 * AST + c * 2) = ONE_F16;
        *(unsigned short*)(smem + buf * ABUF + TOTROW * AST + c * 2) = ONE_F16;
    }

    // ---- build chunk 0 into buffer 0 (set-only; buffer pre-zeroed) ----
    const int pS = tid >> 5, cS0 = (tid & 31) * 4;   // ones scatter mapping
    {
        if (tid < 320) {
            uchar4 nb = *(const uchar4*)(binp + pS * TT + cS0);
            const unsigned char* nk = (const unsigned char*)&nb;
            #pragma unroll
            for (int e = 0; e < 4; ++e)
                if (nk[e] < KB17)
                    *(unsigned short*)(smem + (unsigned)(pS * KB17 + nk[e]) * AST +
                                       (cS0 + e) * 2) = ONE_F16;
        }
        const int a0i = tid >> 5, tq0 = tid & 31;
        float4 f0 = *(const float4*)(amp + ampBase + (long)a0i * (SSEG*TT) + tq0 * 4);
        storeB_item(smem, f0, tid, 0);
        if (tid < 448) {
            const int a1i = (tid + 512) >> 5, tq1 = (tid + 512) & 31;
            float4 f1 = *(const float4*)(amp + ampBase + (long)a1i * (SSEG*TT) + tq1 * 4);
            storeB_item(smem, f1, tid + 512, 0);
        }
    }
    __syncthreads();

    // ---- MMA mainloop: K-split 4 x M-split 4 (tiles 3/3/3/2), double-buffered ----
    const int kg = wid & 3, mg = wid >> 2;
    const int MTC = (mg == 3) ? 2 : 3;
    const unsigned aAddrOff = (unsigned)(mg * 48 + (lane & 15)) * AST +
                              (((lane >> 4) & 1) << 4);              // +16B if k-half hi
    const unsigned nrow  = (lane & 7) + (((lane >> 4) & 1) << 3);
    const unsigned kadd2 = (((lane >> 3) & 1) << 4);                 // +16B if k-half hi
    float acc[3][4][4];
    #pragma unroll
    for (int mt = 0; mt < 3; ++mt)
        #pragma unroll
        for (int nt = 0; nt < 4; ++nt)
            #pragma unroll
            for (int e = 0; e < 4; ++e) acc[mt][nt][e] = 0.f;

    for (int i = 0; i < NCHUNK; ++i) {
        const int buf = i & 1, nbuf = buf ^ 1;
        const int t0 = i * CK;
        float4 pf0, pf1;
        if (i + 1 < NCHUNK) {  // prefetch next amp chunk (lands during MMA)
            const int a0i = tid >> 5, tq0 = tid & 31;
            pf0 = *(const float4*)(amp + ampBase + (long)a0i * (SSEG*TT) + t0 + CK + tq0 * 4);
            if (tid < 448) {
                const int a1i = (tid + 512) >> 5, tq1 = (tid + 512) & 31;
                pf1 = *(const float4*)(amp + ampBase + (long)a1i * (SSEG*TT) + t0 + CK + tq1 * 4);
            }
        }
        // MMA on buf
        const unsigned aAddrBase = sb + (unsigned)buf * ABUF + aAddrOff;
        const unsigned bBase = sb + B_OFF + (unsigned)buf * BBUF;
        if (MTC == 3) mma_steps<3>(aAddrBase, bBase, kg, nrow, kadd2, acc);
        else          mma_steps<2>(aAddrBase, bBase, kg, nrow, kadd2, acc);
        // build chunk i+1 into nbuf (overlaps MMA issue; no extra sync needed)
        if (i + 1 < NCHUNK) {
            if (tid < 320) {
                unsigned char* an = smem + (unsigned)nbuf * ABUF;
                if (i >= 1) {   // clear chunk i-1's ones (last written into nbuf)
                    uchar4 ob = *(const uchar4*)(binp + pS * TT + (t0 - CK) + cS0);
                    const unsigned char* ok = (const unsigned char*)&ob;
                    #pragma unroll
                    for (int e = 0; e < 4; ++e)
                        if (ok[e] < KB17)
                            *(unsigned short*)(an + (unsigned)(pS * KB17 + ok[e]) * AST +
                                               (cS0 + e) * 2) = 0;
                }
                uchar4 nb = *(const uchar4*)(binp + pS * TT + t0 + CK + cS0);
                const unsigned char* nk = (const unsigned char*)&nb;
                #pragma unroll
                for (int e = 0; e < 4; ++e)
                    if (nk[e] < KB17)
                        *(unsigned short*)(an + (unsigned)(pS * KB17 + nk[e]) * AST +
                                           (cS0 + e) * 2) = ONE_F16;
            }
            storeB_item(smem, pf0, tid, nbuf);
            if (tid < 448) storeB_item(smem, pf1, tid + 512, nbuf);
        }
        __syncthreads();
    }

    // ---- K-split reduction (deterministic, stride-33 conflict-free) ----
    const int rrow = lane >> 2, rcol = (lane & 3) * 2;
    if (kg) {
        float* dst = (float*)smem + (unsigned)(kg - 1) * DRED_STRIDE;
        for (int mt = 0; mt < MTC; ++mt)
            #pragma unroll
            for (int nt = 0; nt < 4; ++nt) {
                const int row = mg * 48 + mt * 16 + rrow, col = nt * 8 + rcol;
                dst[row * 33 + col]           = acc[mt][nt][0];
                dst[row * 33 + col + 1]       = acc[mt][nt][1];
                dst[(row + 8) * 33 + col]     = acc[mt][nt][2];
                dst[(row + 8) * 33 + col + 1] = acc[mt][nt][3];
            }
    }
    __syncthreads();
    if (!kg) {
        float* Dfin = (float*)(smem + DFIN_OFF);
        const float* dr = (const float*)smem;
        for (int mt = 0; mt < MTC; ++mt)
            #pragma unroll
            for (int nt = 0; nt < 4; ++nt) {
                const int row = mg * 48 + mt * 16 + rrow, col = nt * 8 + rcol;
                const int i0 = row * 33 + col, i2 = (row + 8) * 33 + col;
                Dfin[i0]     = acc[mt][nt][0] + dr[i0] + dr[DRED_STRIDE + i0] + dr[2*DRED_STRIDE + i0];
                Dfin[i0 + 1] = acc[mt][nt][1] + dr[i0+1] + dr[DRED_STRIDE + i0+1] + dr[2*DRED_STRIDE + i0+1];
                Dfin[i2]     = acc[mt][nt][2] + dr[i2] + dr[DRED_STRIDE + i2] + dr[2*DRED_STRIDE + i2];
                Dfin[i2 + 1] = acc[mt][nt][3] + dr[i2+1] + dr[DRED_STRIDE + i2+1] + dr[2*DRED_STRIDE + i2+1];
            }
    }
    __syncthreads();

    // ---- epilogue per (p,a); counts in col 30; bin 17 derived from totals ----
    if (tid < FP * FA) {
        const float* Dfin = (const float*)(smem + DFIN_OFF);
        const int p = tid / FA;
        const int a = tid - p * FA;
        float meanv[NBINS];
        float tot = 0.f, sSum = 0.f, cSum = 0.f;
        #pragma unroll
        for (int k = 0; k < KB17; ++k) {
            const float sv = Dfin[(p * KB17 + k) * 33 + a];
            const float cf = Dfin[(p * KB17 + k) * 33 + 30];
            sSum += sv;
            cSum += cf;
            const float m = sv / (cf + 1e-9f);
            meanv[k] = m;
            tot += m;
        }
        {   // bin 17: totals-row minus the rest (counts are exact integers in f32)
            const float s17 = Dfin[TOTROW * 33 + a] - sSum;
            const float c17 = 2048.0f - cSum;
            const float m17 = (c17 < 0.5f) ? 0.f : s17 / (c17 + 1e-9f);
            meanv[17] = m17;
            tot += m17;
        }
        const float inv = 1.0f / (tot + 1e-9f);
        float ent = 0.f;
        #pragma unroll
        for (int k = 0; k < NBINS; ++k) {
            const float pr = meanv[k] * inv;
            ent += pr * logf(pr + 1e-9f);
        }
        const float L18 = 2.8903717578961645f;  // log(18)
        g_partial[((long)(bc * FP + p) * FA + a) * SSEG + s] = (L18 + ent) / L18;
    }
}

__global__ void mi_mean_kernel(float* __restrict__ out)
{
    int i = blockIdx.x * blockDim.x + threadIdx.x;
    if (i < BB*CC*FP*FA) {
        const float* p = g_partial + (long)i * SSEG;
        out[i] = (p[0] + p[1] + p[2] + p[3]) * 0.25f;
    }
}

extern "C" void kernel_launch(void* const* d_in, const int* in_sizes, int n_in,
                              void* d_out, int out_size)
{
    const float* pha = (const float*)d_in[0];
    const float* amp = (const float*)d_in[1];
    if (n_in >= 2 && in_sizes[0] > in_sizes[1]) {   // defensive: pha is smaller
        const float* t = pha; pha = amp; amp = t;
    }
    (void)cudaFuncSetAttribute(mi_mma_kernel,
                               cudaFuncAttributeMaxDynamicSharedMemorySize, SMEM_BYTES);
    mi_mma_kernel<<<BB*CC*SSEG, NTH, SMEM_BYTES>>>(pha, amp);
    mi_mean_kernel<<<(BB*CC*FP*FA + 255) / 256, 256>>>((float*)d_out);
}

// round 16
// speedup vs baseline: 1.4808x; 1.4808x over previous
#include <cuda_runtime.h>
#include <cuda_bf16.h>
#include <cuda_fp16.h>
#include <math.h>

// Problem dims
#define BB 4
#define CC 16
#define FP 10
#define FA 30
#define SSEG 4
#define TT 2048
#define NBINS 18
#define KB17 17           // bins materialized per p (bin 17 derived)

#define NTH 512           // 16 warps
#define CK 128            // t per chunk
#define NCHUNK 16

// SMEM layout (bytes). A: 176 rows x 128 cols fp16, row stride 272 B. Two buffers.
// Rows: p*17+k (k<17) for p=0..9 -> 0..169; row 170 = all-ones totals row;
// rows 171..175 zero pad.
#define AST 272
#define MROWS 176
#define TOTROW 170
#define ABUF (MROWS*AST)          // 47872
#define B_OFF (2*ABUF)            // 95744; two B buffers: 32 x 272 fp16 each
#define BBUF 8704
#define BIN_OFF (B_OFF + 2*BBUF)  // 113152; 10*2048 bin bytes
#define ZERO_BYTES BIN_OFF
#define SMEM_BYTES (BIN_OFF + FP*TT)   // 133632
// Epilogue overlays A region (dead by then)
#define DRED_STRIDE (MROWS*33)    // floats
#define DFIN_OFF (3*MROWS*33*4)   // 69696 bytes

#define ONE_F16 0x3C00

__device__ float g_partial[BB*CC*FP*FA*SSEG];

__device__ __forceinline__ unsigned smem_u32(const void* p) {
    unsigned r;
    asm("{ .reg .u64 t; cvta.to.shared.u64 t, %1; cvt.u32.u64 %0, t; }"
        : "=r"(r) : "l"(p));
    return r;
}
__device__ __forceinline__ void ldsm_x4(unsigned addr, unsigned& r0, unsigned& r1,
                                        unsigned& r2, unsigned& r3) {
    asm volatile("ldmatrix.sync.aligned.m8n8.x4.shared.b16 {%0,%1,%2,%3}, [%4];"
                 : "=r"(r0), "=r"(r1), "=r"(r2), "=r"(r3) : "r"(addr));
}
__device__ __forceinline__ void mma16816(float* c, unsigned a0, unsigned a1,
                                         unsigned a2, unsigned a3,
                                         unsigned b0, unsigned b1) {
    asm volatile("mma.sync.aligned.m16n8k16.row.col.f32.f16.f16.f32 "
                 "{%0,%1,%2,%3}, {%4,%5,%6,%7}, {%8,%9}, {%0,%1,%2,%3};"
                 : "+f"(c[0]), "+f"(c[1]), "+f"(c[2]), "+f"(c[3])
                 : "r"(a0), "r"(a1), "r"(a2), "r"(a3), "r"(b0), "r"(b1));
}

// One chunk's MMA work for MT m-tiles (both k-halves of this warp's K slice).
// MT is a compile-time constant; all acc indexing constant -> register-resident.
template<int MT>
__device__ __forceinline__ void mma_steps(unsigned aAddrBase, unsigned bBase,
                                          int kg, unsigned nrow, unsigned kadd2,
                                          float acc[3][4][4]) {
    #pragma unroll
    for (int ks = 0; ks < 2; ++ks) {
        const int k0 = kg * 32 + ks * 16;
        unsigned a0[MT], a1[MT], a2[MT], a3[MT];
        #pragma unroll
        for (int mt = 0; mt < MT; ++mt)
            ldsm_x4(aAddrBase + mt * 16 * AST + k0 * 2, a0[mt], a1[mt], a2[mt], a3[mt]);
        unsigned bh[8];
        #pragma unroll
        for (int np = 0; np < 2; ++np) {
            const unsigned bOff = (unsigned)(np * 16 + nrow) * AST + k0 * 2 + kadd2;
            ldsm_x4(bBase + bOff, bh[np*4], bh[np*4+1], bh[np*4+2], bh[np*4+3]);
        }
        #pragma unroll
        for (int mt = 0; mt < MT; ++mt)
            #pragma unroll
            for (int nt = 0; nt < 4; ++nt) {
                const int bi = (nt >> 1) * 4 + (nt & 1) * 2;
                mma16816(acc[mt][nt], a0[mt], a1[mt], a2[mt], a3[mt], bh[bi], bh[bi+1]);
            }
    }
}

__device__ __forceinline__ void storeB_item(unsigned char* smem, float4 v, int item,
                                            int buf) {
    const int a = item >> 5, tq = item & 31;
    __half2 p01 = __floats2half2_rn(v.x, v.y);
    __half2 p23 = __floats2half2_rn(v.z, v.w);
    uint2 w = make_uint2(*(const unsigned*)&p01, *(const unsigned*)&p23);
    *(uint2*)(smem + B_OFF + buf * BBUF + a * AST + tq * 8) = w;
}

__global__ __launch_bounds__(NTH, 1)
void mi_mma_kernel(const float* __restrict__ pha, const float* __restrict__ amp)
{
    extern __shared__ __align__(16) unsigned char smem[];
    const unsigned sb = smem_u32(smem);
    const int tid = threadIdx.x, wid = tid >> 5, lane = tid & 31;
    const int bcs = blockIdx.x, s = bcs & 3, bc = bcs >> 2;
    const long phaBase = (long)bc * FP * (SSEG*TT) + (long)s * TT;
    const long ampBase = (long)bc * FA * (SSEG*TT) + (long)s * TT;
    unsigned char* binp = smem + BIN_OFF;

    // zero both A buffers + both B buffers
    for (int i = tid; i < ZERO_BYTES / 16; i += NTH)
        ((uint4*)smem)[i] = make_uint4(0, 0, 0, 0);

    // ---- phase 1: exact searchsorted bins -> binp[p*2048 + t] ----
    const float PI_F = 3.14159265358979323846f;
    const float step = __fdiv_rn(2.0f * PI_F, (float)NBINS);
    const float inv_step = 1.0f / step;
    #pragma unroll
    for (int p = 0; p < FP; ++p) {
        const float4 v4 = *(const float4*)(pha + phaBase + (long)p * (SSEG*TT) + (long)tid * 4);
        const float vv[4] = {v4.x, v4.y, v4.z, v4.w};
        uchar4 kb;
        unsigned char* kk = (unsigned char*)&kb;
        #pragma unroll
        for (int e = 0; e < 4; ++e) {
            const float v = vv[e];
            int k = (int)floorf((v + PI_F) * inv_step);
            k = min(max(k, 0), NBINS - 1);
            // guess is provably within +-1 bin: one exact fixup suffices
            {
                float ck  = __fadd_rn(-PI_F, __fmul_rn((float)k,       step));
                float ck1 = __fadd_rn(-PI_F, __fmul_rn((float)(k + 1), step));
                if (k > 0 && v <= ck)              k--;
                else if (k < NBINS - 1 && v > ck1) k++;
            }
            kk[e] = (unsigned char)k;
        }
        *(uchar4*)(binp + p * TT + tid * 4) = kb;
    }
    __syncthreads();

    // ones rows: B row 30 (counts channel) + A row 170 (totals row), both buffers
    if (tid < 256) {
        const int buf = tid >> 7, c = tid & 127;
        *(unsigned short*)(smem + B_OFF + buf * BBUF + 30 * AST + c * 2) = ONE_F16;
        *(unsigned short*)(smem + buf * ABUF + TOTROW * AST + c * 2) = ONE_F16;
    }

    // ---- build chunk 0 into buffer 0 (set-only; buffer pre-zeroed) ----
    const int pS = tid >> 5, cS0 = (tid & 31) * 4;   // ones scatter mapping
    {
        if (tid < 320) {
            uchar4 nb = *(const uchar4*)(binp + pS * TT + cS0);
            const unsigned char* nk = (const unsigned char*)&nb;
            #pragma unroll
            for (int e = 0; e < 4; ++e)
                if (nk[e] < KB17)
                    *(unsigned short*)(smem + (unsigned)(pS * KB17 + nk[e]) * AST +
                                       (cS0 + e) * 2) = ONE_F16;
        }
        const int a0i = tid >> 5, tq0 = tid & 31;
        float4 f0 = *(const float4*)(amp + ampBase + (long)a0i * (SSEG*TT) + tq0 * 4);
        storeB_item(smem, f0, tid, 0);
        if (tid < 448) {
            const int a1i = (tid + 512) >> 5, tq1 = (tid + 512) & 31;
            float4 f1 = *(const float4*)(amp + ampBase + (long)a1i * (SSEG*TT) + tq1 * 4);
            storeB_item(smem, f1, tid + 512, 0);
        }
    }
    __syncthreads();

    // ---- MMA mainloop: K-split 4 x M-split 4 (tiles 3/3/3/2), double-buffered ----
    const int kg = wid & 3, mg = wid >> 2;
    const int MTC = (mg == 3) ? 2 : 3;
    const unsigned aAddrOff = (unsigned)(mg * 48 + (lane & 15)) * AST +
                              (((lane >> 4) & 1) << 4);              // +16B if k-half hi
    const unsigned nrow  = (lane & 7) + (((lane >> 4) & 1) << 3);
    const unsigned kadd2 = (((lane >> 3) & 1) << 4);                 // +16B if k-half hi
    float acc[3][4][4];
    #pragma unroll
    for (int mt = 0; mt < 3; ++mt)
        #pragma unroll
        for (int nt = 0; nt < 4; ++nt)
            #pragma unroll
            for (int e = 0; e < 4; ++e) acc[mt][nt][e] = 0.f;

    for (int i = 0; i < NCHUNK; ++i) {
        const int buf = i & 1, nbuf = buf ^ 1;
        const int t0 = i * CK;
        float4 pf0, pf1;
        if (i + 1 < NCHUNK) {  // prefetch next amp chunk (lands during MMA)
            const int a0i = tid >> 5, tq0 = tid & 31;
            pf0 = *(const float4*)(amp + ampBase + (long)a0i * (SSEG*TT) + t0 + CK + tq0 * 4);
            if (tid < 448) {
                const int a1i = (tid + 512) >> 5, tq1 = (tid + 512) & 31;
                pf1 = *(const float4*)(amp + ampBase + (long)a1i * (SSEG*TT) + t0 + CK + tq1 * 4);
            }
        }
        // MMA on buf
        const unsigned aAddrBase = sb + (unsigned)buf * ABUF + aAddrOff;
        const unsigned bBase = sb + B_OFF + (unsigned)buf * BBUF;
        if (MTC == 3) mma_steps<3>(aAddrBase, bBase, kg, nrow, kadd2, acc);
        else          mma_steps<2>(aAddrBase, bBase, kg, nrow, kadd2, acc);
        // build chunk i+1 into nbuf (overlaps MMA issue; no extra sync needed)
        if (i + 1 < NCHUNK) {
            if (tid < 320) {
                unsigned char* an = smem + (unsigned)nbuf * ABUF;
                if (i >= 1) {   // clear chunk i-1's ones (last written into nbuf)
                    uchar4 ob = *(const uchar4*)(binp + pS * TT + (t0 - CK) + cS0);
                    const unsigned char* ok = (const unsigned char*)&ob;
                    #pragma unroll
                    for (int e = 0; e < 4; ++e)
                        if (ok[e] < KB17)
                            *(unsigned short*)(an + (unsigned)(pS * KB17 + ok[e]) * AST +
                                               (cS0 + e) * 2) = 0;
                }
                uchar4 nb = *(const uchar4*)(binp + pS * TT + t0 + CK + cS0);
                const unsigned char* nk = (const unsigned char*)&nb;
                #pragma unroll
                for (int e = 0; e < 4; ++e)
                    if (nk[e] < KB17)
                        *(unsigned short*)(an + (unsigned)(pS * KB17 + nk[e]) * AST +
                                           (cS0 + e) * 2) = ONE_F16;
            }
            storeB_item(smem, pf0, tid, nbuf);
            if (tid < 448) storeB_item(smem, pf1, tid + 512, nbuf);
        }
        __syncthreads();
    }

    // ---- K-split reduction (deterministic, stride-33 conflict-free) ----
    // NOTE: constant-bound unrolled loops with uniform guard -> acc stays in
    // registers (runtime loop bound here caused a full local-memory spill in R15).
    const int rrow = lane >> 2, rcol = (lane & 3) * 2;
    if (kg) {
        float* dst = (float*)smem + (unsigned)(kg - 1) * DRED_STRIDE;
        #pragma unroll
        for (int mt = 0; mt < 3; ++mt) {
            if (mt < MTC) {
                #pragma unroll
                for (int nt = 0; nt < 4; ++nt) {
                    const int row = mg * 48 + mt * 16 + rrow, col = nt * 8 + rcol;
                    dst[row * 33 + col]           = acc[mt][nt][0];
                    dst[row * 33 + col + 1]       = acc[mt][nt][1];
                    dst[(row + 8) * 33 + col]     = acc[mt][nt][2];
                    dst[(row + 8) * 33 + col + 1] = acc[mt][nt][3];
                }
            }
        }
    }
    __syncthreads();
    if (!kg) {
        float* Dfin = (float*)(smem + DFIN_OFF);
        const float* dr = (const float*)smem;
        #pragma unroll
        for (int mt = 0; mt < 3; ++mt) {
            if (mt < MTC) {
                #pragma unroll
                for (int nt = 0; nt < 4; ++nt) {
                    const int row = mg * 48 + mt * 16 + rrow, col = nt * 8 + rcol;
                    const int i0 = row * 33 + col, i2 = (row + 8) * 33 + col;
                    Dfin[i0]     = acc[mt][nt][0] + dr[i0] + dr[DRED_STRIDE + i0] + dr[2*DRED_STRIDE + i0];
                    Dfin[i0 + 1] = acc[mt][nt][1] + dr[i0+1] + dr[DRED_STRIDE + i0+1] + dr[2*DRED_STRIDE + i0+1];
                    Dfin[i2]     = acc[mt][nt][2] + dr[i2] + dr[DRED_STRIDE + i2] + dr[2*DRED_STRIDE + i2];
                    Dfin[i2 + 1] = acc[mt][nt][3] + dr[i2+1] + dr[DRED_STRIDE + i2+1] + dr[2*DRED_STRIDE + i2+1];
                }
            }
        }
    }
    __syncthreads();

    // ---- epilogue per (p,a); counts in col 30; bin 17 derived from totals ----
    if (tid < FP * FA) {
        const float* Dfin = (const float*)(smem + DFIN_OFF);
        const int p = tid / FA;
        const int a = tid - p * FA;
        float meanv[NBINS];
        float tot = 0.f, sSum = 0.f, cSum = 0.f;
        #pragma unroll
        for (int k = 0; k < KB17; ++k) {
            const float sv = Dfin[(p * KB17 + k) * 33 + a];
            const float cf = Dfin[(p * KB17 + k) * 33 + 30];
            sSum += sv;
            cSum += cf;
            const float m = sv / (cf + 1e-9f);
            meanv[k] = m;
            tot += m;
        }
        {   // bin 17: totals-row minus the rest (counts are exact integers in f32)
            const float s17 = Dfin[TOTROW * 33 + a] - sSum;
            const float c17 = 2048.0f - cSum;
            const float m17 = (c17 < 0.5f) ? 0.f : s17 / (c17 + 1e-9f);
            meanv[17] = m17;
            tot += m17;
        }
        const float inv = 1.0f / (tot + 1e-9f);
        float ent = 0.f;
        #pragma unroll
        for (int k = 0; k < NBINS; ++k) {
            const float pr = meanv[k] * inv;
            ent += pr * logf(pr + 1e-9f);
        }
        const float L18 = 2.8903717578961645f;  // log(18)
        g_partial[((long)(bc * FP + p) * FA + a) * SSEG + s] = (L18 + ent) / L18;
    }
}

__global__ void mi_mean_kernel(float* __restrict__ out)
{
    int i = blockIdx.x * blockDim.x + threadIdx.x;
    if (i < BB*CC*FP*FA) {
        const float* p = g_partial + (long)i * SSEG;
        out[i] = (p[0] + p[1] + p[2] + p[3]) * 0.25f;
    }
}

extern "C" void kernel_launch(void* const* d_in, const int* in_sizes, int n_in,
                              void* d_out, int out_size)
{
    const float* pha = (const float*)d_in[0];
    const float* amp = (const float*)d_in[1];
    if (n_in >= 2 && in_sizes[0] > in_sizes[1]) {   // defensive: pha is smaller
        const float* t = pha; pha = amp; amp = t;
    }
    (void)cudaFuncSetAttribute(mi_mma_kernel,
                               cudaFuncAttributeMaxDynamicSharedMemorySize, SMEM_BYTES);
    mi_mma_kernel<<<BB*CC*SSEG, NTH, SMEM_BYTES>>>(pha, amp);
    mi_mean_kernel<<<(BB*CC*FP*FA + 255) / 256, 256>>>((float*)d_out);
}